// round 12
// baseline (speedup 1.0000x reference)
#include <cuda_runtime.h>
#include <math.h>

#define NN  10000
#define EE  50000
#define BB  4
#define KK  16
#define DD  64
#define RR  200
#define LL  3
#define E2C (2*EE)
#define NT  (BB*NN)
#define ETC (BB*E2C)
#define KSN 4000
#define ESN 40000
#define MAPNEGINF 0x007FFFFFu

__device__ int      g_src[ETC];
__device__ int      g_dst[ETC];
__device__ int      g_attr[ETC];
__device__ int      g_rowptr[NT+1];
__device__ int      g_cursor[NT];
__device__ int      g_csr[ETC];
__device__ int      g_degfull[NT];
__device__ float    g_score[NT];
__device__ float    g_sig[NT];
__device__ __align__(16) float g_hidden[NT*DD];
__device__ __align__(16) float g_feat[NT*4*DD];
__device__ float    g_degm[NT];
__device__ int      g_active[NT];
__device__ int      g_ncount;
__device__ float    g_pna_mean;
__device__ __align__(16) float g_cvec[DD];
__device__ int      g_hv[BB];
__device__ ulonglong2 g_Wpk2[LL*12*32*32];

__device__ __forceinline__ unsigned mapf(float x) {
    x += 0.0f;
    unsigned u = __float_as_uint(x);
    return (u & 0x80000000u) ? ~u : (u | 0x80000000u);
}
__device__ __forceinline__ unsigned long long pk2(float a, float b) {
    unsigned long long r;
    asm("mov.b64 %0, {%1, %2};" : "=l"(r) : "f"(a), "f"(b));
    return r;
}
__device__ __forceinline__ void upk2(unsigned long long v, float& a, float& b) {
    asm("mov.b64 {%0, %1}, %2;" : "=f"(a), "=f"(b) : "l"(v));
}
__device__ __forceinline__ unsigned long long fma2(unsigned long long a,
                                                   unsigned long long b,
                                                   unsigned long long c) {
    unsigned long long r;
    asm("fma.rn.f32x2 %0, %1, %2, %3;" : "=l"(r) : "l"(a), "l"(b), "l"(c));
    return r;
}

__global__ void k_zero_setup() {
    int i = blockIdx.x * blockDim.x + threadIdx.x;
    if (i < NT) { g_degfull[i] = 0; g_score[i] = 0.0f; }
    if (i == 0) g_ncount = 0;
}

__global__ void k_build_edges(const int* __restrict__ edge_index,
                              const int* __restrict__ edge_attr) {
    int e = blockIdx.x * blockDim.x + threadIdx.x;
    if (e >= ETC) return;
    int eb = e / E2C, j = e - eb * E2C;
    int s, d, a;
    if (j < EE) { s = edge_index[j];       d = edge_index[EE + j]; a = edge_attr[j]; }
    else        { int jj = j - EE;
                  s = edge_index[EE + jj]; d = edge_index[jj];     a = edge_attr[jj]; }
    s += eb * NN; d += eb * NN;
    g_src[e] = s; g_dst[e] = d; g_attr[e] = a;
    atomicAdd(&g_degfull[d], 1);
}

// heads (blocks 0..BB-1) + cvec (block BB); stores g_hv for init_misc's skip
__global__ void k_init_heads_cvec(const int* __restrict__ h_index,
                                  const int* __restrict__ r_index,
                                  const float* __restrict__ hidden_states,
                                  const float* __restrict__ rel_tab,
                                  const float* __restrict__ W_lin, const float* __restrict__ b_lin,
                                  const float* __restrict__ Wm1, const float* __restrict__ bm1,
                                  const float* __restrict__ Wm2, const float* __restrict__ bm2) {
    int b = blockIdx.x, c = threadIdx.x;
    if (b == BB) {
        __shared__ float q[DD];
        q[c] = rel_tab[r_index[0] * DD + c];
        __syncthreads();
        float s = b_lin[c];
        #pragma unroll 8
        for (int i = 0; i < DD; i++) s += q[i] * W_lin[(DD + i) * DD + c];
        g_cvec[c] = s;
        return;
    }
    __shared__ float hs[DD], rl[DD], x[DD], red[DD];
    int hv = h_index[b * KK] + b * NN;
    if (c == 0) g_hv[b] = hv;
    hs[c] = hidden_states[b * DD + c];
    rl[c] = rel_tab[r_index[b * KK] * DD + c];
    __syncthreads();
    g_hidden[hv * DD + c] = hs[c];
    float heur = b_lin[c];
    #pragma unroll 8
    for (int i = 0; i < DD; i++) {
        heur += hs[i] * W_lin[i * DD + c];
        heur += rl[i] * W_lin[(DD + i) * DD + c];
    }
    x[c] = hs[c] * heur;
    __syncthreads();
    float h0 = bm1[c], h1 = bm1[DD + c];
    #pragma unroll 8
    for (int i = 0; i < DD; i++) {
        float xv = x[i];
        h0 += xv * Wm1[i * 2 * DD + c];
        h1 += xv * Wm1[i * 2 * DD + DD + c];
    }
    red[c] = fmaxf(h0, 0.0f) * Wm2[c] + fmaxf(h1, 0.0f) * Wm2[DD + c];
    __syncthreads();
    for (int off = 32; off >= 1; off >>= 1) {
        if (c < off) red[c] += red[c + off];
        __syncthreads();
    }
    if (c == 0) g_score[hv] = red[0] + bm2[0];
}

__global__ void k_scan_rowptr_pna() {
    const int T = 1024, CH = 40;
    __shared__ int sA[T], sB[T];
    __shared__ float sF[T];
    int t = threadIdx.x, base = t * CH, sum = 0;
    float lsum = 0.0f;
    for (int i = 0; i < CH; i++) {
        int idx = base + i;
        if (idx < NT) {
            int dg = g_degfull[idx];
            sum += dg;
            lsum += logf((float)dg + 1.0f);
        }
    }
    sA[t] = sum; sF[t] = lsum;
    __syncthreads();
    int *cur = sA, *nxt = sB;
    for (int off = 1; off < T; off <<= 1) {
        int v = cur[t] + ((t >= off) ? cur[t - off] : 0);
        __syncthreads(); nxt[t] = v; __syncthreads();
        int* tmp = cur; cur = nxt; nxt = tmp;
    }
    int run = cur[t] - sum;
    for (int i = 0; i < CH; i++) {
        int idx = base + i;
        if (idx < NT) { g_rowptr[idx] = run; g_cursor[idx] = run; run += g_degfull[idx]; }
    }
    if (t == T - 1) g_rowptr[NT] = run;
    for (int off = 512; off >= 1; off >>= 1) {
        __syncthreads();
        if (t < off) sF[t] += sF[t + off];
    }
    __syncthreads();
    if (t == 0) g_pna_mean = sF[0] / (float)NT;
}

__global__ void k_scatter() {
    int e = blockIdx.x * blockDim.x + threadIdx.x;
    if (e >= ETC) return;
    int pos = atomicAdd(&g_cursor[g_dst[e]], 1);
    g_csr[pos] = e;
}

// sort each segment by edge id (determinism), then pack src|(attr<<16)
__global__ void k_sort_csr() {
    __shared__ int buf[8][64];
    int gw = (blockIdx.x * blockDim.x + threadIdx.x) >> 5;
    int lane = threadIdx.x & 31;
    int w = (threadIdx.x >> 5) & 7;
    if (gw >= NT) return;
    int p0 = g_rowptr[gw], p1 = g_rowptr[gw + 1];
    int d = p1 - p0;
    if (d <= 0) return;
    if (d > 1) {
        if (d <= 64) {
            for (int i = lane; i < d; i += 32) buf[w][i] = g_csr[p0 + i];
            __syncwarp();
            for (int i = lane; i < d; i += 32) {
                int val = buf[w][i];
                int rank = 0;
                for (int j = 0; j < d; j++) rank += (buf[w][j] < val);
                g_csr[p0 + rank] = val;
            }
        } else if (lane == 0) {
            for (int i = p0 + 1; i < p1; i++) {
                int key = g_csr[i]; int j = i - 1;
                while (j >= p0 && g_csr[j] > key) { g_csr[j + 1] = g_csr[j]; j--; }
                g_csr[j + 1] = key;
            }
        }
        __syncwarp();
    }
    for (int i = lane; i < d; i += 32) {
        int e = g_csr[p0 + i];
        g_csr[p0 + i] = g_src[e] | (g_attr[e] << 16);
    }
}

// hidden init (skips head rows already written by heads) + conv_W repack
__global__ void k_init_misc(const float* __restrict__ text,
                            const float* __restrict__ convW) {
    int i = blockIdx.x * blockDim.x + threadIdx.x;
    if (i < NT * DD) {
        int row = i >> 6;
        if (row != g_hv[0] && row != g_hv[1] && row != g_hv[2] && row != g_hv[3])
            g_hidden[i] = (row < NN) ? text[i] : 0.0f;
    }
    if (i < LL * 12 * 32 * 32) {
        int l = i / (12 * 32 * 32);
        int r = i - l * (12 * 32 * 32);
        int tt = r / (32 * 32);
        int r2 = r - tt * (32 * 32);
        int kkp = r2 >> 5, m = r2 & 31;
        int p = tt >> 2, kc = tt & 3;
        int row0 = p * 256 + kc * 64 + 2 * kkp;
        int i0 = 2 * m;
        const float* Wl = convW + (size_t)l * 768 * 64;
        ulonglong2 v;
        v.x = pk2(Wl[(size_t)row0 * 64 + i0],     Wl[(size_t)(row0 + 1) * 64 + i0]);
        v.y = pk2(Wl[(size_t)row0 * 64 + i0 + 1], Wl[(size_t)(row0 + 1) * 64 + i0 + 1]);
        g_Wpk2[i] = v;
    }
}

__global__ void __launch_bounds__(1024) k_selprep() {
    __shared__ unsigned s_hist[256];
    __shared__ int sA[1024], sB[1024];
    __shared__ unsigned s_prefix, s_thrN, s_thrE;
    __shared__ int s_kk;
    int t = threadIdx.x, lane = t & 31;

    if (t == 0) { s_prefix = 0u; s_kk = KSN; }
    __syncthreads();

    for (int pass = 0; pass < 4; pass++) {
        int shift = 24 - 8 * pass;
        unsigned hi_mask = (pass == 0) ? 0u : (0xFFFFFFFFu << (shift + 8));
        if (t < 256) s_hist[t] = 0u;
        __syncthreads();
        unsigned pfx = s_prefix;
        int kk = s_kk;
        for (int i = t; i < NT; i += 1024) {
            unsigned key = mapf(g_score[i]);
            int bin = -1;
            if (pass == 0 || (key & hi_mask) == pfx)
                bin = (int)((key >> shift) & 0xFFu);
            unsigned mk = __match_any_sync(__activemask(), bin);
            if (bin >= 0 && lane == __ffs(mk) - 1)
                atomicAdd(&s_hist[bin], (unsigned)__popc(mk));
        }
        __syncthreads();
        if (t < 256) sA[t] = (int)s_hist[t];
        __syncthreads();
        int *cur = sA, *nxt = sB;
        for (int off = 1; off < 256; off <<= 1) {
            int v = 0;
            if (t < 256) v = cur[t] + ((t + off < 256) ? cur[t + off] : 0);
            __syncthreads();
            if (t < 256) nxt[t] = v;
            __syncthreads();
            int* tmp = cur; cur = nxt; nxt = tmp;
        }
        if (t < 256) {
            int incl = cur[t];
            int above = (t + 1 < 256) ? cur[t + 1] : 0;
            if (above < kk && incl >= kk) {
                s_prefix = pfx | ((unsigned)t << shift);
                s_kk = kk - above;
            }
        }
        __syncthreads();
    }
    if (t == 0) { s_thrN = s_prefix; s_prefix = 0u; s_kk = ESN; }
    __syncthreads();
    unsigned thrN = s_thrN;

    for (int pass = 0; pass < 4; pass++) {
        int shift = 24 - 8 * pass;
        unsigned hi_mask = (pass == 0) ? 0u : (0xFFFFFFFFu << (shift + 8));
        if (t < 256) s_hist[t] = 0u;
        __syncthreads();
        unsigned pfx = s_prefix;
        int kk = s_kk;
        for (int i = t; i < NT; i += 1024) {
            int w = g_degfull[i];
            unsigned key = mapf(g_score[i]);
            if (key < thrN) key = MAPNEGINF;
            int bin = -1;
            if (w > 0 && (pass == 0 || (key & hi_mask) == pfx))
                bin = (int)((key >> shift) & 0xFFu);
            int wv = (bin >= 0) ? w : 0;
            unsigned mk = __match_any_sync(__activemask(), bin);
            int tot = __reduce_add_sync(mk, wv);
            if (bin >= 0 && lane == __ffs(mk) - 1 && tot > 0)
                atomicAdd(&s_hist[bin], (unsigned)tot);
        }
        __syncthreads();
        if (t < 256) sA[t] = (int)s_hist[t];
        __syncthreads();
        int *cur = sA, *nxt = sB;
        for (int off = 1; off < 256; off <<= 1) {
            int v = 0;
            if (t < 256) v = cur[t] + ((t + off < 256) ? cur[t + off] : 0);
            __syncthreads();
            if (t < 256) nxt[t] = v;
            __syncthreads();
            int* tmp = cur; cur = nxt; nxt = tmp;
        }
        if (t < 256) {
            int incl = cur[t];
            int above = (t + 1 < 256) ? cur[t + 1] : 0;
            if (above < kk && incl >= kk) {
                s_prefix = pfx | ((unsigned)t << shift);
                s_kk = kk - above;
            }
        }
        __syncthreads();
    }
    if (t == 0) s_thrE = s_prefix;
    __syncthreads();
    unsigned thrE = s_thrE;

    int base = t * 40;
    int cnt = 0;
    for (int j = 0; j < 40; j++) {
        int i = base + j;
        if (i < NT) {
            float sc = g_score[i];
            unsigned u = mapf(sc);
            bool pass = (u >= thrN) && (u >= thrE);
            g_sig[i] = pass ? (1.0f / (1.0f + expf(-sc))) : -1.0f;
            if (pass && g_degfull[i] > 0) cnt++;
        }
    }
    sA[t] = cnt;
    __syncthreads();
    int *cur = sA, *nxt = sB;
    for (int off = 1; off < 1024; off <<= 1) {
        int v = cur[t] + ((t >= off) ? cur[t - off] : 0);
        __syncthreads(); nxt[t] = v; __syncthreads();
        int* tmp = cur; cur = nxt; nxt = tmp;
    }
    int woff = cur[t] - cnt;
    for (int j = 0; j < 40; j++) {
        int i = base + j;
        if (i < NT) {
            unsigned u = mapf(g_score[i]);
            if (u >= thrN && u >= thrE && g_degfull[i] > 0) g_active[woff++] = i;
        }
    }
    if (t == 1023) g_ncount = cur[1023];
}

__global__ void k_aggregate(const float* __restrict__ relw) {
    int slot = (blockIdx.x * blockDim.x + threadIdx.x) >> 5;
    int lane = threadIdx.x & 31;
    if (slot >= g_ncount) return;
    int v = g_active[slot];
    int p0 = g_rowptr[v], p1 = g_rowptr[v + 1];
    const float NI = __int_as_float(0xFF800000), PI = __int_as_float(0x7F800000);
    float a0 = 0.f, a1 = 0.f, q0 = 0.f, q1 = 0.f;
    float mx0 = NI, mx1 = NI, mn0 = PI, mn1 = PI;
    int cnt = 0;
    for (int p = p0; p < p1; ++p) {
        int pk = g_csr[p];
        int sv = pk & 0xFFFF;
        float sig = g_sig[sv];
        if (sig < 0.0f) continue;
        cnt++;
        int a = pk >> 16;
        float2 h = *(const float2*)(g_hidden + (size_t)sv * DD + 2 * lane);
        float2 w = *(const float2*)(relw + (size_t)a * DD + 2 * lane);
        float m0 = sig * h.x * w.x;
        float m1 = sig * h.y * w.y;
        a0 += m0; q0 += m0 * m0; mx0 = fmaxf(mx0, m0); mn0 = fminf(mn0, m0);
        a1 += m1; q1 += m1 * m1; mx1 = fmaxf(mx1, m1); mn1 = fminf(mn1, m1);
    }
    float deg = (float)cnt, denom = fmaxf(deg, 1.0f);
    float mean0 = a0 / denom, mean1 = a1 / denom;
    float std0 = sqrtf(fmaxf(q0 / denom - mean0 * mean0, 0.0f) + 1e-6f);
    float std1 = sqrtf(fmaxf(q1 / denom - mean1 * mean1, 0.0f) + 1e-6f);
    if (cnt == 0) { mx0 = mx1 = 0.0f; mn0 = mn1 = 0.0f; }
    float* f = g_feat + (size_t)slot * (4 * DD);
    *(float2*)(f + 2 * lane)          = make_float2(mean0, mean1);
    *(float2*)(f + DD + 2 * lane)     = make_float2(mx0, mx1);
    *(float2*)(f + 2 * DD + 2 * lane) = make_float2(mn0, mn1);
    *(float2*)(f + 3 * DD + 2 * lane) = make_float2(std0, std1);
    if (lane == 0) g_degm[slot] = deg;
}

__global__ void __launch_bounds__(256) k_conv(int l, const float* __restrict__ convb) {
    __shared__ unsigned long long fTn2[64][33];
    __shared__ int nodes_s[64];
    __shared__ float deg_s[64];
    int count = g_ncount;
    int nb = blockIdx.x * 64;
    if (nb >= count) return;
    int tid = threadIdx.x;
    int tx = tid & 15, ty = tid >> 4;
    if (tid < 64) {
        int s = nb + tid;
        nodes_s[tid] = (s < count) ? g_active[s] : -1;
        deg_s[tid]   = (s < count) ? g_degm[s] : 0.0f;
    }
    __syncthreads();
    float pm = g_pna_mean;
    float ampv[4], attv[4];
    #pragma unroll
    for (int j = 0; j < 4; j++) {
        float sl = logf(deg_s[tx + 16 * j] + 1.0f);
        ampv[j] = sl / pm;
        attv[j] = pm / (sl + 1e-6f);
    }
    float fin[4][4] = {};
    for (int p = 0; p < 3; p++) {
        unsigned long long par2[4][4] = {};
        for (int kc = 0; kc < 4; kc++) {
            __syncthreads();
            for (int q = tid; q < 2048; q += 256) {
                int vi = q >> 5, kkp = q & 31;
                unsigned long long val = 0ull;
                int s = nb + vi;
                if (s < count)
                    val = *(const unsigned long long*)(g_feat + (size_t)s * 256 + kc * 64 + 2 * kkp);
                fTn2[vi][kkp] = val;
            }
            __syncthreads();
            const ulonglong2* Wp = g_Wpk2 + (size_t)((l * 12 + p * 4 + kc) * 32) * 32;
            #pragma unroll 8
            for (int kkp = 0; kkp < 32; kkp++) {
                ulonglong2 wA = Wp[kkp * 32 + 2 * ty];
                ulonglong2 wB = Wp[kkp * 32 + 2 * ty + 1];
                #pragma unroll
                for (int j = 0; j < 4; j++) {
                    unsigned long long f2 = fTn2[tx + 16 * j][kkp];
                    par2[j][0] = fma2(f2, wA.x, par2[j][0]);
                    par2[j][1] = fma2(f2, wA.y, par2[j][1]);
                    par2[j][2] = fma2(f2, wB.x, par2[j][2]);
                    par2[j][3] = fma2(f2, wB.y, par2[j][3]);
                }
            }
        }
        #pragma unroll
        for (int j = 0; j < 4; j++) {
            float s_p = (p == 0) ? 1.0f : ((p == 1) ? ampv[j] : attv[j]);
            #pragma unroll
            for (int i2 = 0; i2 < 4; i2++) {
                float lo, hi; upk2(par2[j][i2], lo, hi);
                fin[j][i2] += s_p * (lo + hi);
            }
        }
    }
    float4 bias = *(const float4*)(convb + 4 * ty);
    #pragma unroll
    for (int j = 0; j < 4; j++) {
        int s = nb + tx + 16 * j;
        if (s < count) {
            int nd = nodes_s[tx + 16 * j];
            float4* hp = (float4*)(g_hidden + (size_t)nd * DD + 4 * ty);
            float4 h = *hp;
            h.x += fmaxf(fin[j][0] + bias.x, 0.0f);
            h.y += fmaxf(fin[j][1] + bias.y, 0.0f);
            h.z += fmaxf(fin[j][2] + bias.z, 0.0f);
            h.w += fmaxf(fin[j][3] + bias.w, 0.0f);
            *hp = h;
        }
    }
}

// score v2: warp = column group (broadcast weights), lanes = nodes
__global__ void __launch_bounds__(256) k_score(const float* __restrict__ WlinA,
                        const float* __restrict__ Wm1, const float* __restrict__ bm1,
                        const float* __restrict__ Wm2, const float* __restrict__ bm2) {
    __shared__ float hT[64][65];
    __shared__ float xT[64][65];
    __shared__ float sred[64][9];
    __shared__ int nodes_s[64];
    int count = g_ncount;
    int nb = blockIdx.x * 64;
    if (nb >= count) return;
    int tid = threadIdx.x;
    int lane = tid & 31, w = tid >> 5;
    if (tid < 64) nodes_s[tid] = (nb + tid < count) ? g_active[nb + tid] : -1;
    __syncthreads();
    for (int idx = tid; idx < 4096; idx += 256) {
        int vi = idx >> 6, c = idx & 63;
        int nd = nodes_s[vi];
        hT[c][vi] = (nd >= 0) ? g_hidden[(size_t)nd * DD + c] : 0.0f;
    }
    __syncthreads();

    float acc[2][8] = {};
    #pragma unroll 4
    for (int k = 0; k < 64; k++) {
        float4 wa = *(const float4*)(WlinA + k * 64 + 8 * w);
        float4 wb = *(const float4*)(WlinA + k * 64 + 8 * w + 4);
        float f0 = hT[k][lane], f1 = hT[k][lane + 32];
        acc[0][0] += f0*wa.x; acc[0][1] += f0*wa.y; acc[0][2] += f0*wa.z; acc[0][3] += f0*wa.w;
        acc[0][4] += f0*wb.x; acc[0][5] += f0*wb.y; acc[0][6] += f0*wb.z; acc[0][7] += f0*wb.w;
        acc[1][0] += f1*wa.x; acc[1][1] += f1*wa.y; acc[1][2] += f1*wa.z; acc[1][3] += f1*wa.w;
        acc[1][4] += f1*wb.x; acc[1][5] += f1*wb.y; acc[1][6] += f1*wb.z; acc[1][7] += f1*wb.w;
    }
    {
        float4 ca = *(const float4*)(g_cvec + 8 * w);
        float4 cb = *(const float4*)(g_cvec + 8 * w + 4);
        float cv[8] = {ca.x, ca.y, ca.z, ca.w, cb.x, cb.y, cb.z, cb.w};
        #pragma unroll
        for (int c = 0; c < 8; c++) {
            int col = 8 * w + c;
            xT[col][lane]      = hT[col][lane]      * (acc[0][c] + cv[c]);
            xT[col][lane + 32] = hT[col][lane + 32] * (acc[1][c] + cv[c]);
        }
    }
    __syncthreads();

    float acc2[2][16] = {};
    #pragma unroll 4
    for (int k = 0; k < 64; k++) {
        const float* Wr = Wm1 + k * 128 + 16 * w;
        float4 w0 = *(const float4*)(Wr);
        float4 w1 = *(const float4*)(Wr + 4);
        float4 w2v = *(const float4*)(Wr + 8);
        float4 w3 = *(const float4*)(Wr + 12);
        float f0 = xT[k][lane], f1 = xT[k][lane + 32];
        acc2[0][0]  += f0*w0.x;  acc2[0][1]  += f0*w0.y;  acc2[0][2]  += f0*w0.z;  acc2[0][3]  += f0*w0.w;
        acc2[0][4]  += f0*w1.x;  acc2[0][5]  += f0*w1.y;  acc2[0][6]  += f0*w1.z;  acc2[0][7]  += f0*w1.w;
        acc2[0][8]  += f0*w2v.x; acc2[0][9]  += f0*w2v.y; acc2[0][10] += f0*w2v.z; acc2[0][11] += f0*w2v.w;
        acc2[0][12] += f0*w3.x;  acc2[0][13] += f0*w3.y;  acc2[0][14] += f0*w3.z;  acc2[0][15] += f0*w3.w;
        acc2[1][0]  += f1*w0.x;  acc2[1][1]  += f1*w0.y;  acc2[1][2]  += f1*w0.z;  acc2[1][3]  += f1*w0.w;
        acc2[1][4]  += f1*w1.x;  acc2[1][5]  += f1*w1.y;  acc2[1][6]  += f1*w1.z;  acc2[1][7]  += f1*w1.w;
        acc2[1][8]  += f1*w2v.x; acc2[1][9]  += f1*w2v.y; acc2[1][10] += f1*w2v.z; acc2[1][11] += f1*w2v.w;
        acc2[1][12] += f1*w3.x;  acc2[1][13] += f1*w3.y;  acc2[1][14] += f1*w3.z;  acc2[1][15] += f1*w3.w;
    }
    {
        float b1v[16], m2v[16];
        #pragma unroll
        for (int q = 0; q < 4; q++) {
            float4 bv = *(const float4*)(bm1 + 16 * w + 4 * q);
            float4 mv = *(const float4*)(Wm2 + 16 * w + 4 * q);
            b1v[4*q] = bv.x; b1v[4*q+1] = bv.y; b1v[4*q+2] = bv.z; b1v[4*q+3] = bv.w;
            m2v[4*q] = mv.x; m2v[4*q+1] = mv.y; m2v[4*q+2] = mv.z; m2v[4*q+3] = mv.w;
        }
        float p0 = 0.0f, p1 = 0.0f;
        #pragma unroll
        for (int c = 0; c < 16; c++) {
            p0 += fmaxf(acc2[0][c] + b1v[c], 0.0f) * m2v[c];
            p1 += fmaxf(acc2[1][c] + b1v[c], 0.0f) * m2v[c];
        }
        sred[lane][w] = p0;
        sred[lane + 32][w] = p1;
    }
    __syncthreads();
    if (tid < 64) {
        float s = 0.0f;
        #pragma unroll
        for (int k = 0; k < 8; k++) s += sred[tid][k];
        int nd = nodes_s[tid];
        if (nd >= 0) g_score[nd] = s + bm2[0];
    }
}

__global__ void k_output(const int* __restrict__ t_index, float* __restrict__ out) {
    int i = threadIdx.x;
    if (i < BB * KK) out[i] = g_score[t_index[i] + (i >> 4) * NN];
}

extern "C" void kernel_launch(void* const* d_in, const int* in_sizes, int n_in,
                              void* d_out, int out_size) {
    (void)in_sizes; (void)n_in; (void)out_size;
    const int*   h_index       = (const int*)d_in[0];
    const int*   r_index       = (const int*)d_in[1];
    const int*   t_index       = (const int*)d_in[2];
    const float* hidden_states = (const float*)d_in[3];
    const int*   edge_index    = (const int*)d_in[5];
    const int*   edge_attr     = (const int*)d_in[6];
    const float* text          = (const float*)d_in[7];
    const float* rel_tab       = (const float*)d_in[9];
    const float* W_lin         = (const float*)d_in[10];
    const float* b_lin         = (const float*)d_in[11];
    const float* Wm1           = (const float*)d_in[12];
    const float* bm1           = (const float*)d_in[13];
    const float* Wm2           = (const float*)d_in[14];
    const float* bm2           = (const float*)d_in[15];
    const float* rel_w         = (const float*)d_in[16];
    const float* convW         = (const float*)d_in[17];
    const float* convb         = (const float*)d_in[18];
    float* out = (float*)d_out;

    const int TPB = 256;
    const int GB_E = (ETC + TPB - 1) / TPB;
    const int GB_N = (NT + TPB - 1) / TPB;

    k_zero_setup<<<GB_N, TPB>>>();
    k_build_edges<<<GB_E, TPB>>>(edge_index, edge_attr);
    k_init_heads_cvec<<<BB + 1, 64>>>(h_index, r_index, hidden_states, rel_tab,
                                      W_lin, b_lin, Wm1, bm1, Wm2, bm2);
    k_selprep<<<1, 1024>>>();                       // layer 0; 4th launch -> profiled
    k_scan_rowptr_pna<<<1, 1024>>>();
    k_scatter<<<GB_E, TPB>>>();
    k_sort_csr<<<(NT * 32) / TPB, TPB>>>();
    k_init_misc<<<(NT * DD + TPB - 1) / TPB, TPB>>>(text, convW);

    // layer 0 (selprep already done above)
    k_aggregate<<<(NT * 32) / TPB, TPB>>>(rel_w);
    k_conv<<<NT / 64, 256>>>(0, convb);
    k_score<<<NT / 64, 256>>>(W_lin, Wm1, bm1, Wm2, bm2);
    for (int l = 1; l < LL; l++) {
        k_selprep<<<1, 1024>>>();
        k_aggregate<<<(NT * 32) / TPB, TPB>>>(rel_w + (size_t)l * 2 * RR * DD);
        k_conv<<<NT / 64, 256>>>(l, convb + (size_t)l * DD);
        k_score<<<NT / 64, 256>>>(W_lin, Wm1, bm1, Wm2, bm2);
    }
    k_output<<<1, 64>>>(t_index, out);
}

// round 15
// speedup vs baseline: 1.5881x; 1.5881x over previous
#include <cuda_runtime.h>
#include <math.h>

#define NN  10000
#define EE  50000
#define BB  4
#define KK  16
#define DD  64
#define RR  200
#define LL  3
#define E2C (2*EE)
#define NT  (BB*NN)
#define ETC (BB*E2C)
#define KSN 4000
#define ESN 40000
#define MAPNEGINF 0x007FFFFFu
#define GRIDB 40          // 40*1024 = 40960 >= NT; all blocks co-resident (148 SMs)

__device__ int      g_src[ETC];
__device__ int      g_dst[ETC];
__device__ int      g_attr[ETC];
__device__ int      g_rowptr[NT+1];
__device__ int      g_cursor[NT];
__device__ int      g_csr[ETC];
__device__ int      g_degfull[NT];
__device__ float    g_score[NT];
__device__ float    g_sig[NT];
__device__ __align__(16) float g_hidden[NT*DD];
__device__ __align__(16) float g_feat[NT*4*DD];
__device__ float    g_degm[NT];
__device__ int      g_active[NT];
__device__ int      g_ncount;
__device__ float    g_pna_mean;
__device__ __align__(16) float g_cvec[DD];
__device__ int      g_hv[BB];
__device__ ulonglong2 g_Wpk2[LL*12*32*32];
// select machinery
__device__ unsigned g_hist8[8*256];
__device__ int      g_blkcnt[GRIDB];
__device__ unsigned g_bar_count;
__device__ volatile unsigned g_bar_phase;

__device__ __forceinline__ unsigned mapf(float x) {
    x += 0.0f;
    unsigned u = __float_as_uint(x);
    return (u & 0x80000000u) ? ~u : (u | 0x80000000u);
}
__device__ __forceinline__ unsigned long long pk2(float a, float b) {
    unsigned long long r;
    asm("mov.b64 %0, {%1, %2};" : "=l"(r) : "f"(a), "f"(b));
    return r;
}
__device__ __forceinline__ void upk2(unsigned long long v, float& a, float& b) {
    asm("mov.b64 {%0, %1}, %2;" : "=f"(a), "=f"(b) : "l"(v));
}
__device__ __forceinline__ unsigned long long fma2(unsigned long long a,
                                                   unsigned long long b,
                                                   unsigned long long c) {
    unsigned long long r;
    asm("fma.rn.f32x2 %0, %1, %2, %3;" : "=l"(r) : "l"(a), "l"(b), "l"(c));
    return r;
}

// software grid barrier: all GRIDB blocks co-resident (1 block/SM).
// gen read BEFORE arrival atomic; count reset fenced before phase bump.
__device__ __forceinline__ void grid_barrier() {
    __threadfence();
    __syncthreads();
    if (threadIdx.x == 0) {
        unsigned gen = g_bar_phase;
        if (atomicAdd(&g_bar_count, 1u) == GRIDB - 1) {
            g_bar_count = 0u;
            __threadfence();
            g_bar_phase = gen + 1u;
        } else {
            while (g_bar_phase == gen) { __nanosleep(64); }
        }
        __threadfence();
    }
    __syncthreads();
}

__global__ void k_zero_setup() {
    int i = blockIdx.x * blockDim.x + threadIdx.x;
    if (i < NT) { g_degfull[i] = 0; g_score[i] = 0.0f; }
    if (i < 8 * 256) g_hist8[i] = 0u;
    if (i == 0) { g_ncount = 0; g_bar_count = 0u; g_bar_phase = 0u; }
}

__global__ void k_build_edges(const int* __restrict__ edge_index,
                              const int* __restrict__ edge_attr) {
    int e = blockIdx.x * blockDim.x + threadIdx.x;
    if (e >= ETC) return;
    int eb = e / E2C, j = e - eb * E2C;
    int s, d, a;
    if (j < EE) { s = edge_index[j];       d = edge_index[EE + j]; a = edge_attr[j]; }
    else        { int jj = j - EE;
                  s = edge_index[EE + jj]; d = edge_index[jj];     a = edge_attr[jj]; }
    s += eb * NN; d += eb * NN;
    g_src[e] = s; g_dst[e] = d; g_attr[e] = a;
    atomicAdd(&g_degfull[d], 1);
}

__global__ void k_init_heads_cvec(const int* __restrict__ h_index,
                                  const int* __restrict__ r_index,
                                  const float* __restrict__ hidden_states,
                                  const float* __restrict__ rel_tab,
                                  const float* __restrict__ W_lin, const float* __restrict__ b_lin,
                                  const float* __restrict__ Wm1, const float* __restrict__ bm1,
                                  const float* __restrict__ Wm2, const float* __restrict__ bm2) {
    int b = blockIdx.x, c = threadIdx.x;
    if (b == BB) {
        __shared__ float q[DD];
        q[c] = rel_tab[r_index[0] * DD + c];
        __syncthreads();
        float s = b_lin[c];
        #pragma unroll 8
        for (int i = 0; i < DD; i++) s += q[i] * W_lin[(DD + i) * DD + c];
        g_cvec[c] = s;
        return;
    }
    __shared__ float hs[DD], rl[DD], x[DD], red[DD];
    int hv = h_index[b * KK] + b * NN;
    if (c == 0) g_hv[b] = hv;
    hs[c] = hidden_states[b * DD + c];
    rl[c] = rel_tab[r_index[b * KK] * DD + c];
    __syncthreads();
    g_hidden[hv * DD + c] = hs[c];
    float heur = b_lin[c];
    #pragma unroll 8
    for (int i = 0; i < DD; i++) {
        heur += hs[i] * W_lin[i * DD + c];
        heur += rl[i] * W_lin[(DD + i) * DD + c];
    }
    x[c] = hs[c] * heur;
    __syncthreads();
    float h0 = bm1[c], h1 = bm1[DD + c];
    #pragma unroll 8
    for (int i = 0; i < DD; i++) {
        float xv = x[i];
        h0 += xv * Wm1[i * 2 * DD + c];
        h1 += xv * Wm1[i * 2 * DD + DD + c];
    }
    red[c] = fmaxf(h0, 0.0f) * Wm2[c] + fmaxf(h1, 0.0f) * Wm2[DD + c];
    __syncthreads();
    for (int off = 32; off >= 1; off >>= 1) {
        if (c < off) red[c] += red[c + off];
        __syncthreads();
    }
    if (c == 0) g_score[hv] = red[0] + bm2[0];
}

// ------- multi-block fused select + sigmoid + compaction (GRIDB x 1024) -------
__global__ void __launch_bounds__(1024) k_selprep_all() {
    __shared__ int sA[1024], sB[1024];
    __shared__ unsigned s_pfx;
    __shared__ int s_kk;
    __shared__ int s_blk[GRIDB];
    int t = threadIdx.x, bid = blockIdx.x;
    int lane = t & 31;
    int i = bid * 1024 + t;

    float sc = 0.0f;
    unsigned key_n = 0u;
    int wdeg = 0;
    if (i < NT) {
        sc = g_score[i];
        key_n = mapf(sc);
        wdeg = g_degfull[i];
    }

    unsigned pfx = 0u, thrN = 0u, thrE = 0u;
    int kk = KSN;
    for (int round = 0; round < 8; round++) {
        bool edge = (round >= 4);
        int pass = round & 3;
        if (round == 4) { pfx = 0u; kk = ESN; }
        int shift = 24 - 8 * pass;
        unsigned key = key_n;
        if (edge && key < thrN) key = MAPNEGINF;
        bool valid = (i < NT) && (!edge || wdeg > 0);
        int bin = -1;
        if (valid && (pass == 0 || (key >> (shift + 8)) == (pfx >> (shift + 8))))
            bin = (int)((key >> shift) & 0xFFu);
        unsigned mk = __match_any_sync(0xFFFFFFFFu, bin);
        int tot;
        if (!edge) tot = __popc(mk);
        else       tot = __reduce_add_sync(mk, (bin >= 0) ? wdeg : 0);
        if (bin >= 0 && lane == __ffs(mk) - 1 && tot > 0)
            atomicAdd(&g_hist8[round * 256 + bin], (unsigned)tot);

        grid_barrier();

        sA[t] = (t < 256) ? (int)__ldcg((const unsigned*)&g_hist8[round * 256 + t]) : 0;
        __syncthreads();
        int *cur = sA, *nxt = sB;
        for (int off = 1; off < 256; off <<= 1) {
            int v = 0;
            if (t < 256) v = cur[t] + ((t + off < 256) ? cur[t + off] : 0);
            __syncthreads();
            if (t < 256) nxt[t] = v;
            __syncthreads();
            int* tmp = cur; cur = nxt; nxt = tmp;
        }
        if (t < 256) {
            int incl = cur[t];
            int above = (t + 1 < 256) ? cur[t + 1] : 0;
            if (above < kk && incl >= kk) {           // exactly one thread
                s_pfx = pfx | ((unsigned)t << shift);
                s_kk = kk - above;
            }
        }
        __syncthreads();
        pfx = s_pfx;
        kk = s_kk;
        __syncthreads();
        if (round == 3) thrN = pfx;
        if (round == 7) thrE = pfx;
    }

    bool passes = (i < NT) && (key_n >= thrN) && (key_n >= thrE);
    if (i < NT) g_sig[i] = passes ? (1.0f / (1.0f + expf(-sc))) : -1.0f;
    int act = (passes && wdeg > 0) ? 1 : 0;

    sA[t] = act;
    __syncthreads();
    int *cur = sA, *nxt = sB;
    for (int off = 1; off < 1024; off <<= 1) {
        int v = cur[t] + ((t >= off) ? cur[t - off] : 0);
        __syncthreads(); nxt[t] = v; __syncthreads();
        int* tmp = cur; cur = nxt; nxt = tmp;
    }
    int myexcl = cur[t] - act;
    if (t == 1023) g_blkcnt[bid] = cur[1023];

    grid_barrier();

    if (t < GRIDB) s_blk[t] = __ldcg(&g_blkcnt[t]);
    __syncthreads();
    int boff = 0;
    for (int b = 0; b < bid; b++) boff += s_blk[b];
    if (act) g_active[boff + myexcl] = i;
    if (bid == 0 && t == 0) {
        int total = 0;
        for (int b = 0; b < GRIDB; b++) total += s_blk[b];
        g_ncount = total;
    }
    for (int q = bid * 1024 + t; q < 8 * 256; q += GRIDB * 1024) g_hist8[q] = 0u;
}

__global__ void k_scan_rowptr_pna() {
    const int T = 1024, CH = 40;
    __shared__ int sA[T], sB[T];
    __shared__ float sF[T];
    int t = threadIdx.x, base = t * CH, sum = 0;
    float lsum = 0.0f;
    for (int i = 0; i < CH; i++) {
        int idx = base + i;
        if (idx < NT) {
            int dg = g_degfull[idx];
            sum += dg;
            lsum += logf((float)dg + 1.0f);
        }
    }
    sA[t] = sum; sF[t] = lsum;
    __syncthreads();
    int *cur = sA, *nxt = sB;
    for (int off = 1; off < T; off <<= 1) {
        int v = cur[t] + ((t >= off) ? cur[t - off] : 0);
        __syncthreads(); nxt[t] = v; __syncthreads();
        int* tmp = cur; cur = nxt; nxt = tmp;
    }
    int run = cur[t] - sum;
    for (int i = 0; i < CH; i++) {
        int idx = base + i;
        if (idx < NT) { g_rowptr[idx] = run; g_cursor[idx] = run; run += g_degfull[idx]; }
    }
    if (t == T - 1) g_rowptr[NT] = run;
    for (int off = 512; off >= 1; off >>= 1) {
        __syncthreads();
        if (t < off) sF[t] += sF[t + off];
    }
    __syncthreads();
    if (t == 0) g_pna_mean = sF[0] / (float)NT;
}

__global__ void k_scatter() {
    int e = blockIdx.x * blockDim.x + threadIdx.x;
    if (e >= ETC) return;
    int pos = atomicAdd(&g_cursor[g_dst[e]], 1);
    g_csr[pos] = e;
}

__global__ void k_sort_csr() {
    __shared__ int buf[8][64];
    int gw = (blockIdx.x * blockDim.x + threadIdx.x) >> 5;
    int lane = threadIdx.x & 31;
    int w = (threadIdx.x >> 5) & 7;
    if (gw >= NT) return;
    int p0 = g_rowptr[gw], p1 = g_rowptr[gw + 1];
    int d = p1 - p0;
    if (d <= 0) return;
    if (d > 1) {
        if (d <= 64) {
            for (int i = lane; i < d; i += 32) buf[w][i] = g_csr[p0 + i];
            __syncwarp();
            for (int i = lane; i < d; i += 32) {
                int val = buf[w][i];
                int rank = 0;
                for (int j = 0; j < d; j++) rank += (buf[w][j] < val);
                g_csr[p0 + rank] = val;
            }
        } else if (lane == 0) {
            for (int i = p0 + 1; i < p1; i++) {
                int key = g_csr[i]; int j = i - 1;
                while (j >= p0 && g_csr[j] > key) { g_csr[j + 1] = g_csr[j]; j--; }
                g_csr[j + 1] = key;
            }
        }
        __syncwarp();
    }
    for (int i = lane; i < d; i += 32) {
        int e = g_csr[p0 + i];
        g_csr[p0 + i] = g_src[e] | (g_attr[e] << 16);
    }
}

__global__ void k_init_misc(const float* __restrict__ text,
                            const float* __restrict__ convW) {
    int i = blockIdx.x * blockDim.x + threadIdx.x;
    if (i < NT * DD) {
        int row = i >> 6;
        if (row != g_hv[0] && row != g_hv[1] && row != g_hv[2] && row != g_hv[3])
            g_hidden[i] = (row < NN) ? text[i] : 0.0f;
    }
    if (i < LL * 12 * 32 * 32) {
        int l = i / (12 * 32 * 32);
        int r = i - l * (12 * 32 * 32);
        int tt = r / (32 * 32);
        int r2 = r - tt * (32 * 32);
        int kkp = r2 >> 5, m = r2 & 31;
        int p = tt >> 2, kc = tt & 3;
        int row0 = p * 256 + kc * 64 + 2 * kkp;
        int i0 = 2 * m;
        const float* Wl = convW + (size_t)l * 768 * 64;
        ulonglong2 v;
        v.x = pk2(Wl[(size_t)row0 * 64 + i0],     Wl[(size_t)(row0 + 1) * 64 + i0]);
        v.y = pk2(Wl[(size_t)row0 * 64 + i0 + 1], Wl[(size_t)(row0 + 1) * 64 + i0 + 1]);
        g_Wpk2[i] = v;
    }
}

__global__ void k_aggregate(const float* __restrict__ relw) {
    int slot = (blockIdx.x * blockDim.x + threadIdx.x) >> 5;
    int lane = threadIdx.x & 31;
    if (slot >= g_ncount) return;
    int v = g_active[slot];
    int p0 = g_rowptr[v], p1 = g_rowptr[v + 1];
    const float NI = __int_as_float(0xFF800000), PI = __int_as_float(0x7F800000);
    float a0 = 0.f, a1 = 0.f, q0 = 0.f, q1 = 0.f;
    float mx0 = NI, mx1 = NI, mn0 = PI, mn1 = PI;
    int cnt = 0;
    for (int p = p0; p < p1; ++p) {
        int pk = g_csr[p];
        int sv = pk & 0xFFFF;
        float sig = g_sig[sv];
        if (sig < 0.0f) continue;
        cnt++;
        int a = pk >> 16;
        float2 h = *(const float2*)(g_hidden + (size_t)sv * DD + 2 * lane);
        float2 w = *(const float2*)(relw + (size_t)a * DD + 2 * lane);
        float m0 = sig * h.x * w.x;
        float m1 = sig * h.y * w.y;
        a0 += m0; q0 += m0 * m0; mx0 = fmaxf(mx0, m0); mn0 = fminf(mn0, m0);
        a1 += m1; q1 += m1 * m1; mx1 = fmaxf(mx1, m1); mn1 = fminf(mn1, m1);
    }
    float deg = (float)cnt, denom = fmaxf(deg, 1.0f);
    float mean0 = a0 / denom, mean1 = a1 / denom;
    float std0 = sqrtf(fmaxf(q0 / denom - mean0 * mean0, 0.0f) + 1e-6f);
    float std1 = sqrtf(fmaxf(q1 / denom - mean1 * mean1, 0.0f) + 1e-6f);
    if (cnt == 0) { mx0 = mx1 = 0.0f; mn0 = mn1 = 0.0f; }
    float* f = g_feat + (size_t)slot * (4 * DD);
    *(float2*)(f + 2 * lane)          = make_float2(mean0, mean1);
    *(float2*)(f + DD + 2 * lane)     = make_float2(mx0, mx1);
    *(float2*)(f + 2 * DD + 2 * lane) = make_float2(mn0, mn1);
    *(float2*)(f + 3 * DD + 2 * lane) = make_float2(std0, std1);
    if (lane == 0) g_degm[slot] = deg;
}

__global__ void __launch_bounds__(256) k_conv(int l, const float* __restrict__ convb) {
    __shared__ unsigned long long fTn2[64][33];
    __shared__ int nodes_s[64];
    __shared__ float deg_s[64];
    int count = g_ncount;
    int nb = blockIdx.x * 64;
    if (nb >= count) return;
    int tid = threadIdx.x;
    int tx = tid & 15, ty = tid >> 4;
    if (tid < 64) {
        int s = nb + tid;
        nodes_s[tid] = (s < count) ? g_active[s] : -1;
        deg_s[tid]   = (s < count) ? g_degm[s] : 0.0f;
    }
    __syncthreads();
    float pm = g_pna_mean;
    float ampv[4], attv[4];
    #pragma unroll
    for (int j = 0; j < 4; j++) {
        float sl = logf(deg_s[tx + 16 * j] + 1.0f);
        ampv[j] = sl / pm;
        attv[j] = pm / (sl + 1e-6f);
    }
    float fin[4][4] = {};
    for (int p = 0; p < 3; p++) {
        unsigned long long par2[4][4] = {};
        for (int kc = 0; kc < 4; kc++) {
            __syncthreads();
            for (int q = tid; q < 2048; q += 256) {
                int vi = q >> 5, kkp = q & 31;
                unsigned long long val = 0ull;
                int s = nb + vi;
                if (s < count)
                    val = *(const unsigned long long*)(g_feat + (size_t)s * 256 + kc * 64 + 2 * kkp);
                fTn2[vi][kkp] = val;
            }
            __syncthreads();
            const ulonglong2* Wp = g_Wpk2 + (size_t)((l * 12 + p * 4 + kc) * 32) * 32;
            #pragma unroll 8
            for (int kkp = 0; kkp < 32; kkp++) {
                ulonglong2 wA = Wp[kkp * 32 + 2 * ty];
                ulonglong2 wB = Wp[kkp * 32 + 2 * ty + 1];
                #pragma unroll
                for (int j = 0; j < 4; j++) {
                    unsigned long long f2 = fTn2[tx + 16 * j][kkp];
                    par2[j][0] = fma2(f2, wA.x, par2[j][0]);
                    par2[j][1] = fma2(f2, wA.y, par2[j][1]);
                    par2[j][2] = fma2(f2, wB.x, par2[j][2]);
                    par2[j][3] = fma2(f2, wB.y, par2[j][3]);
                }
            }
        }
        #pragma unroll
        for (int j = 0; j < 4; j++) {
            float s_p = (p == 0) ? 1.0f : ((p == 1) ? ampv[j] : attv[j]);
            #pragma unroll
            for (int i2 = 0; i2 < 4; i2++) {
                float lo, hi; upk2(par2[j][i2], lo, hi);
                fin[j][i2] += s_p * (lo + hi);
            }
        }
    }
    float4 bias = *(const float4*)(convb + 4 * ty);
    #pragma unroll
    for (int j = 0; j < 4; j++) {
        int s = nb + tx + 16 * j;
        if (s < count) {
            int nd = nodes_s[tx + 16 * j];
            float4* hp = (float4*)(g_hidden + (size_t)nd * DD + 4 * ty);
            float4 h = *hp;
            h.x += fmaxf(fin[j][0] + bias.x, 0.0f);
            h.y += fmaxf(fin[j][1] + bias.y, 0.0f);
            h.z += fmaxf(fin[j][2] + bias.z, 0.0f);
            h.w += fmaxf(fin[j][3] + bias.w, 0.0f);
            *hp = h;
        }
    }
}

__global__ void __launch_bounds__(256) k_score(const float* __restrict__ WlinA,
                        const float* __restrict__ Wm1, const float* __restrict__ bm1,
                        const float* __restrict__ Wm2, const float* __restrict__ bm2) {
    __shared__ float hT[64][65];
    __shared__ float xT[64][65];
    __shared__ float sred[64][9];
    __shared__ int nodes_s[64];
    int count = g_ncount;
    int nb = blockIdx.x * 64;
    if (nb >= count) return;
    int tid = threadIdx.x;
    int lane = tid & 31, w = tid >> 5;
    if (tid < 64) nodes_s[tid] = (nb + tid < count) ? g_active[nb + tid] : -1;
    __syncthreads();
    for (int idx = tid; idx < 4096; idx += 256) {
        int vi = idx >> 6, c = idx & 63;
        int nd = nodes_s[vi];
        hT[c][vi] = (nd >= 0) ? g_hidden[(size_t)nd * DD + c] : 0.0f;
    }
    __syncthreads();

    float acc[2][8] = {};
    #pragma unroll 4
    for (int k = 0; k < 64; k++) {
        float4 wa = *(const float4*)(WlinA + k * 64 + 8 * w);
        float4 wb = *(const float4*)(WlinA + k * 64 + 8 * w + 4);
        float f0 = hT[k][lane], f1 = hT[k][lane + 32];
        acc[0][0] += f0*wa.x; acc[0][1] += f0*wa.y; acc[0][2] += f0*wa.z; acc[0][3] += f0*wa.w;
        acc[0][4] += f0*wb.x; acc[0][5] += f0*wb.y; acc[0][6] += f0*wb.z; acc[0][7] += f0*wb.w;
        acc[1][0] += f1*wa.x; acc[1][1] += f1*wa.y; acc[1][2] += f1*wa.z; acc[1][3] += f1*wa.w;
        acc[1][4] += f1*wb.x; acc[1][5] += f1*wb.y; acc[1][6] += f1*wb.z; acc[1][7] += f1*wb.w;
    }
    {
        float4 ca = *(const float4*)(g_cvec + 8 * w);
        float4 cb = *(const float4*)(g_cvec + 8 * w + 4);
        float cv[8] = {ca.x, ca.y, ca.z, ca.w, cb.x, cb.y, cb.z, cb.w};
        #pragma unroll
        for (int c = 0; c < 8; c++) {
            int col = 8 * w + c;
            xT[col][lane]      = hT[col][lane]      * (acc[0][c] + cv[c]);
            xT[col][lane + 32] = hT[col][lane + 32] * (acc[1][c] + cv[c]);
        }
    }
    __syncthreads();

    float acc2[2][16] = {};
    #pragma unroll 4
    for (int k = 0; k < 64; k++) {
        const float* Wr = Wm1 + k * 128 + 16 * w;
        float4 w0 = *(const float4*)(Wr);
        float4 w1 = *(const float4*)(Wr + 4);
        float4 w2v = *(const float4*)(Wr + 8);
        float4 w3 = *(const float4*)(Wr + 12);
        float f0 = xT[k][lane], f1 = xT[k][lane + 32];
        acc2[0][0]  += f0*w0.x;  acc2[0][1]  += f0*w0.y;  acc2[0][2]  += f0*w0.z;  acc2[0][3]  += f0*w0.w;
        acc2[0][4]  += f0*w1.x;  acc2[0][5]  += f0*w1.y;  acc2[0][6]  += f0*w1.z;  acc2[0][7]  += f0*w1.w;
        acc2[0][8]  += f0*w2v.x; acc2[0][9]  += f0*w2v.y; acc2[0][10] += f0*w2v.z; acc2[0][11] += f0*w2v.w;
        acc2[0][12] += f0*w3.x;  acc2[0][13] += f0*w3.y;  acc2[0][14] += f0*w3.z;  acc2[0][15] += f0*w3.w;
        acc2[1][0]  += f1*w0.x;  acc2[1][1]  += f1*w0.y;  acc2[1][2]  += f1*w0.z;  acc2[1][3]  += f1*w0.w;
        acc2[1][4]  += f1*w1.x;  acc2[1][5]  += f1*w1.y;  acc2[1][6]  += f1*w1.z;  acc2[1][7]  += f1*w1.w;
        acc2[1][8]  += f1*w2v.x; acc2[1][9]  += f1*w2v.y; acc2[1][10] += f1*w2v.z; acc2[1][11] += f1*w2v.w;
        acc2[1][12] += f1*w3.x;  acc2[1][13] += f1*w3.y;  acc2[1][14] += f1*w3.z;  acc2[1][15] += f1*w3.w;
    }
    {
        float b1v[16], m2v[16];
        #pragma unroll
        for (int q = 0; q < 4; q++) {
            float4 bv = *(const float4*)(bm1 + 16 * w + 4 * q);
            float4 mv = *(const float4*)(Wm2 + 16 * w + 4 * q);
            b1v[4*q] = bv.x; b1v[4*q+1] = bv.y; b1v[4*q+2] = bv.z; b1v[4*q+3] = bv.w;
            m2v[4*q] = mv.x; m2v[4*q+1] = mv.y; m2v[4*q+2] = mv.z; m2v[4*q+3] = mv.w;
        }
        float p0 = 0.0f, p1 = 0.0f;
        #pragma unroll
        for (int c = 0; c < 16; c++) {
            p0 += fmaxf(acc2[0][c] + b1v[c], 0.0f) * m2v[c];
            p1 += fmaxf(acc2[1][c] + b1v[c], 0.0f) * m2v[c];
        }
        sred[lane][w] = p0;
        sred[lane + 32][w] = p1;
    }
    __syncthreads();
    if (tid < 64) {
        float s = 0.0f;
        #pragma unroll
        for (int k = 0; k < 8; k++) s += sred[tid][k];
        int nd = nodes_s[tid];
        if (nd >= 0) g_score[nd] = s + bm2[0];
    }
}

__global__ void k_output(const int* __restrict__ t_index, float* __restrict__ out) {
    int i = threadIdx.x;
    if (i < BB * KK) out[i] = g_score[t_index[i] + (i >> 4) * NN];
}

extern "C" void kernel_launch(void* const* d_in, const int* in_sizes, int n_in,
                              void* d_out, int out_size) {
    (void)in_sizes; (void)n_in; (void)out_size;
    const int*   h_index       = (const int*)d_in[0];
    const int*   r_index       = (const int*)d_in[1];
    const int*   t_index       = (const int*)d_in[2];
    const float* hidden_states = (const float*)d_in[3];
    const int*   edge_index    = (const int*)d_in[5];
    const int*   edge_attr     = (const int*)d_in[6];
    const float* text          = (const float*)d_in[7];
    const float* rel_tab       = (const float*)d_in[9];
    const float* W_lin         = (const float*)d_in[10];
    const float* b_lin         = (const float*)d_in[11];
    const float* Wm1           = (const float*)d_in[12];
    const float* bm1           = (const float*)d_in[13];
    const float* Wm2           = (const float*)d_in[14];
    const float* bm2           = (const float*)d_in[15];
    const float* rel_w         = (const float*)d_in[16];
    const float* convW         = (const float*)d_in[17];
    const float* convb         = (const float*)d_in[18];
    float* out = (float*)d_out;

    const int TPB = 256;
    const int GB_E = (ETC + TPB - 1) / TPB;
    const int GB_N = (NT + TPB - 1) / TPB;

    k_zero_setup<<<GB_N, TPB>>>();
    k_build_edges<<<GB_E, TPB>>>(edge_index, edge_attr);
    k_init_heads_cvec<<<BB + 1, 64>>>(h_index, r_index, hidden_states, rel_tab,
                                      W_lin, b_lin, Wm1, bm1, Wm2, bm2);
    k_selprep_all<<<GRIDB, 1024>>>();               // layer 0; 4th launch -> profiled
    k_scan_rowptr_pna<<<1, 1024>>>();
    k_scatter<<<GB_E, TPB>>>();
    k_sort_csr<<<(NT * 32) / TPB, TPB>>>();
    k_init_misc<<<(NT * DD + TPB - 1) / TPB, TPB>>>(text, convW);

    // layer 0 (select already done above)
    k_aggregate<<<(NT * 32) / TPB, TPB>>>(rel_w);
    k_conv<<<NT / 64, 256>>>(0, convb);
    k_score<<<NT / 64, 256>>>(W_lin, Wm1, bm1, Wm2, bm2);
    for (int l = 1; l < LL; l++) {
        k_selprep_all<<<GRIDB, 1024>>>();
        k_aggregate<<<(NT * 32) / TPB, TPB>>>(rel_w + (size_t)l * 2 * RR * DD);
        k_conv<<<NT / 64, 256>>>(l, convb + (size_t)l * DD);
        k_score<<<NT / 64, 256>>>(W_lin, Wm1, bm1, Wm2, bm2);
    }
    k_output<<<1, 64>>>(t_index, out);
}